// round 1
// baseline (speedup 1.0000x reference)
#include <cuda_runtime.h>
#include <cstdint>

// Problem constants
#define Bn 4
#define Cn 32
#define Ln 256
#define Mn 256
#define Fn 8
#define Nn 64
#define FC (Fn * Cn)          // 256
#define LM (Ln * Mn)          // 65536
#define IMAG_OFF ((size_t)Bn * Fn * LM)  // 2,097,152

// Scratch: per-l interpolated weights, pre-duplicated as f32x2 pairs.
// Layout: [l][3][FC] where 3 = { {wr,wr}, {wi,wi}, {-wi,-wi} }, each 8 bytes.
__device__ unsigned long long g_w[Ln * 3 * FC];   // 1.5 MB

union U64 {
    unsigned long long u;
    float2 f;
};

__device__ __forceinline__ unsigned long long ffma2(unsigned long long a,
                                                    unsigned long long b,
                                                    unsigned long long c) {
    unsigned long long d;
    asm("fma.rn.f32x2 %0, %1, %2, %3;" : "=l"(d) : "l"(a), "l"(b), "l"(c));
    return d;
}

// ---------------------------------------------------------------------------
// Kernel 1: interpolate weights along N->L once, write duplicated f32x2 pairs.
// total items = L * F * C = 65536
// ---------------------------------------------------------------------------
__global__ void interp_weights_kernel(const float* __restrict__ wr,
                                      const float* __restrict__ wi) {
    int idx = blockIdx.x * blockDim.x + threadIdx.x;   // [0, 65536)
    int l = idx >> 8;          // / FC
    int k = idx & (FC - 1);    // f*C + c

    const float step = 63.0f / 255.0f;
    float t = (float)l * step;
    int lo = (int)t;
    if (lo > Nn - 2) lo = Nn - 2;
    float fr = t - (float)lo;
    float om = 1.0f - fr;

    const float* pr = wr + k * Nn;
    const float* pi = wi + k * Nn;
    float vr = pr[lo] * om + pr[lo + 1] * fr;
    float vi = pi[lo] * om + pi[lo + 1] * fr;

    U64 ur, ui, un;
    ur.f = make_float2(vr, vr);
    ui.f = make_float2(vi, vi);
    un.f = make_float2(-vi, -vi);

    size_t base = (size_t)l * (3 * FC);
    g_w[base + k]          = ur.u;
    g_w[base + FC + k]     = ui.u;
    g_w[base + 2 * FC + k] = un.u;
}

// ---------------------------------------------------------------------------
// Kernel 2: main contraction.
// Grid: B*L = 1024 blocks, 64 threads. Each thread handles 4 consecutive m.
// out[part][b][f][l][m], part 0 = relu(real), part 1 = imag.
// ---------------------------------------------------------------------------
__global__ __launch_bounds__(64) void sphere_main_kernel(
    const float* __restrict__ xr,
    const float* __restrict__ xi,
    float* __restrict__ out) {
    __shared__ unsigned long long s[3 * FC];   // 6 KB

    int bid = blockIdx.x;
    int b = bid >> 8;        // / L
    int l = bid & (Ln - 1);
    int tid = threadIdx.x;

    // Coalesced copy of this l's 768 weight pairs (6 KB) into shared.
    {
        const unsigned long long* g = g_w + (size_t)l * (3 * FC);
#pragma unroll
        for (int i = 0; i < 12; ++i)
            s[tid + i * 64] = g[tid + i * 64];
    }
    __syncthreads();

    int m0 = tid * 4;
    const float* pr = xr + ((size_t)b * Cn) * LM + (size_t)l * Mn + m0;
    const float* pi = xi + ((size_t)b * Cn) * LM + (size_t)l * Mn + m0;

    unsigned long long ar[Fn][2], ai[Fn][2];
#pragma unroll
    for (int f = 0; f < Fn; ++f) {
        ar[f][0] = 0ull; ar[f][1] = 0ull;
        ai[f][0] = 0ull; ai[f][1] = 0ull;
    }

#pragma unroll 4
    for (int c = 0; c < Cn; ++c) {
        longlong2 vr = *reinterpret_cast<const longlong2*>(pr + (size_t)c * LM);
        longlong2 vi = *reinterpret_cast<const longlong2*>(pi + (size_t)c * LM);
        unsigned long long xr01 = (unsigned long long)vr.x;
        unsigned long long xr23 = (unsigned long long)vr.y;
        unsigned long long xi01 = (unsigned long long)vi.x;
        unsigned long long xi23 = (unsigned long long)vi.y;

#pragma unroll
        for (int f = 0; f < Fn; ++f) {
            int k = f * Cn + c;
            unsigned long long w_r = s[k];            // {wr, wr}
            unsigned long long w_i = s[FC + k];       // {wi, wi}
            unsigned long long w_n = s[2 * FC + k];   // {-wi, -wi}

            // real: wr*xr - wi*xi
            ar[f][0] = ffma2(w_r, xr01, ar[f][0]);
            ar[f][0] = ffma2(w_n, xi01, ar[f][0]);
            ar[f][1] = ffma2(w_r, xr23, ar[f][1]);
            ar[f][1] = ffma2(w_n, xi23, ar[f][1]);
            // imag: wr*xi + wi*xr
            ai[f][0] = ffma2(w_r, xi01, ai[f][0]);
            ai[f][0] = ffma2(w_i, xr01, ai[f][0]);
            ai[f][1] = ffma2(w_r, xi23, ai[f][1]);
            ai[f][1] = ffma2(w_i, xr23, ai[f][1]);
        }
    }

    float sc = sqrtf(1.0f + (float)l) * (1.0f / 32.0f);
    float* o_real = out + (size_t)b * Fn * LM + (size_t)l * Mn + m0;
    float* o_imag = o_real + IMAG_OFF;

#pragma unroll
    for (int f = 0; f < Fn; ++f) {
        U64 u0, u1;
        u0.u = ar[f][0]; u1.u = ar[f][1];
        float4 vr4;
        vr4.x = fmaxf(u0.f.x * sc, 0.0f);
        vr4.y = fmaxf(u0.f.y * sc, 0.0f);
        vr4.z = fmaxf(u1.f.x * sc, 0.0f);
        vr4.w = fmaxf(u1.f.y * sc, 0.0f);
        *reinterpret_cast<float4*>(o_real + (size_t)f * LM) = vr4;

        u0.u = ai[f][0]; u1.u = ai[f][1];
        float4 vi4;
        vi4.x = u0.f.x * sc;
        vi4.y = u0.f.y * sc;
        vi4.z = u1.f.x * sc;
        vi4.w = u1.f.y * sc;
        *reinterpret_cast<float4*>(o_imag + (size_t)f * LM) = vi4;
    }
}

extern "C" void kernel_launch(void* const* d_in, const int* in_sizes, int n_in,
                              void* d_out, int out_size) {
    const float* x_real = (const float*)d_in[0];
    const float* x_imag = (const float*)d_in[1];
    const float* w_real = (const float*)d_in[2];
    const float* w_imag = (const float*)d_in[3];
    float* out = (float*)d_out;

    interp_weights_kernel<<<256, 256>>>(w_real, w_imag);
    sphere_main_kernel<<<Bn * Ln, 64>>>(x_real, x_imag, out);
}

// round 2
// speedup vs baseline: 1.0986x; 1.0986x over previous
#include <cuda_runtime.h>
#include <cstdint>

// Problem constants
#define Bn 4
#define Cn 32
#define Ln 256
#define Mn 256
#define Fn 8
#define Nn 64
#define FC (Fn * Cn)          // 256
#define LM (Ln * Mn)          // 65536
#define IMAG_OFF ((size_t)Bn * Fn * LM)  // 2,097,152

union U64 {
    unsigned long long u;
    float2 f;
};

__device__ __forceinline__ unsigned long long ffma2(unsigned long long a,
                                                    unsigned long long b,
                                                    unsigned long long c) {
    unsigned long long d;
    asm("fma.rn.f32x2 %0, %1, %2, %3;" : "=l"(d) : "l"(a), "l"(b), "l"(c));
    return d;
}

// ---------------------------------------------------------------------------
// Fused kernel: per-block weight interpolation into shared, then contraction.
// Grid: B*L = 1024 blocks, 128 threads. Each thread handles 2 consecutive m.
// Shared weights: s2[k] = { {wr,wr}, {wi,wi} } (one LDS.128 per (c,f)).
// out[part][b][f][l][m], part 0 = relu(real), part 1 = imag.
// ---------------------------------------------------------------------------
__global__ __launch_bounds__(128) void sphere_fused_kernel(
    const float* __restrict__ xr,
    const float* __restrict__ xi,
    const float* __restrict__ wr,
    const float* __restrict__ wi,
    float* __restrict__ out) {
    __shared__ ulonglong2 s2[FC];   // 4 KB

    int bid = blockIdx.x;
    int b = bid >> 8;        // / L
    int l = bid & (Ln - 1);
    int tid = threadIdx.x;

    // --- interpolate this l's weights (N=64 grid -> position t) ---
    {
        float t = (float)l * (63.0f / 255.0f);
        int lo = (int)t;
        if (lo > Nn - 2) lo = Nn - 2;
        float fr = t - (float)lo;
        float om = 1.0f - fr;
#pragma unroll
        for (int j = 0; j < 2; ++j) {
            int k = tid + j * 128;            // k = f*C + c in [0, 256)
            const float* pwr = wr + k * Nn + lo;
            const float* pwi = wi + k * Nn + lo;
            float vr = pwr[0] * om + pwr[1] * fr;
            float vi = pwi[0] * om + pwi[1] * fr;
            U64 ur, ui;
            ur.f = make_float2(vr, vr);
            ui.f = make_float2(vi, vi);
            s2[k] = make_ulonglong2(ur.u, ui.u);
        }
    }
    __syncthreads();

    int m0 = tid * 2;
    const float* pr = xr + (size_t)b * Cn * LM + (size_t)l * Mn + m0;
    const float* pi = xi + (size_t)b * Cn * LM + (size_t)l * Mn + m0;

    unsigned long long ar[Fn], ai[Fn];
#pragma unroll
    for (int f = 0; f < Fn; ++f) { ar[f] = 0ull; ai[f] = 0ull; }

    // prefetch c = 0
    unsigned long long xr_n = *reinterpret_cast<const unsigned long long*>(pr);
    unsigned long long xi_n = *reinterpret_cast<const unsigned long long*>(pi);

#pragma unroll 4
    for (int c = 0; c < Cn; ++c) {
        unsigned long long xrc = xr_n;
        unsigned long long xic = xi_n;
        if (c < Cn - 1) {
            pr += LM; pi += LM;
            xr_n = *reinterpret_cast<const unsigned long long*>(pr);
            xi_n = *reinterpret_cast<const unsigned long long*>(pi);
        }
        // nxi = -xi (flip both sign bits)
        unsigned long long nxi = xic ^ 0x8000000080000000ULL;

#pragma unroll
        for (int f = 0; f < Fn; ++f) {
            ulonglong2 w = s2[f * Cn + c];    // one LDS.128: {wr,wr},{wi,wi}
            // real: wr*xr - wi*xi
            ar[f] = ffma2(w.x, xrc, ar[f]);
            ar[f] = ffma2(w.y, nxi, ar[f]);
            // imag: wr*xi + wi*xr
            ai[f] = ffma2(w.x, xic, ai[f]);
            ai[f] = ffma2(w.y, xrc, ai[f]);
        }
    }

    float sc = sqrtf(1.0f + (float)l) * (1.0f / 32.0f);
    float* o_real = out + (size_t)b * Fn * LM + (size_t)l * Mn + m0;
    float* o_imag = o_real + IMAG_OFF;

#pragma unroll
    for (int f = 0; f < Fn; ++f) {
        U64 u;
        u.u = ar[f];
        float2 vr2;
        vr2.x = fmaxf(u.f.x * sc, 0.0f);
        vr2.y = fmaxf(u.f.y * sc, 0.0f);
        *reinterpret_cast<float2*>(o_real + (size_t)f * LM) = vr2;

        u.u = ai[f];
        float2 vi2;
        vi2.x = u.f.x * sc;
        vi2.y = u.f.y * sc;
        *reinterpret_cast<float2*>(o_imag + (size_t)f * LM) = vi2;
    }
}

extern "C" void kernel_launch(void* const* d_in, const int* in_sizes, int n_in,
                              void* d_out, int out_size) {
    const float* x_real = (const float*)d_in[0];
    const float* x_imag = (const float*)d_in[1];
    const float* w_real = (const float*)d_in[2];
    const float* w_imag = (const float*)d_in[3];
    float* out = (float*)d_out;

    sphere_fused_kernel<<<Bn * Ln, 128>>>(x_real, x_imag, w_real, w_imag, out);
}